// round 5
// baseline (speedup 1.0000x reference)
#include <cuda_runtime.h>

#define NF 24
#define ED 16
#define AS 32
#define NPAIR 276
#define NPP 288          /* padded pairs */
#define NPACK 144        /* NPP/2 */
#define TPB 192
#define PG 48            /* pair-groups */
#define AG 4             /* a-groups */
#define AR 8             /* a-values per thread */
#define PK 3             /* packs (of 2 pairs) per thread */

typedef unsigned long long u64;

__device__ int g_x64_flag;

__global__ void detect_dtype_kernel(const unsigned int* __restrict__ xraw) {
    if (threadIdx.x == 0) {
        unsigned int acc = 0;
        #pragma unroll 1
        for (int k = 0; k < 64; k++) acc |= xraw[2 * k + 1];
        g_x64_flag = (acc == 0u) ? 1 : 0;
    }
}

__device__ __forceinline__ u64 fma2(u64 a, u64 b, u64 c) {
    u64 d;
    asm("fma.rn.f32x2 %0, %1, %2, %3;" : "=l"(d) : "l"(a), "l"(b), "l"(c));
    return d;
}
__device__ __forceinline__ void unpack2(u64 v, float& lo, float& hi) {
    asm("mov.b64 {%0, %1}, %2;" : "=f"(lo), "=f"(hi) : "l"(v));
}
__device__ __forceinline__ u64 pack2(float lo, float hi) {
    u64 d;
    asm("mov.b64 %0, {%1, %2};" : "=l"(d) : "f"(lo), "f"(hi));
    return d;
}

// pair index -> (row, col) for 24 fields, triu k=1, row-major pair order
__device__ __forceinline__ void pair_rc(int p, int& r, int& c) {
    int q = 275 - p;
    float s = sqrtf((float)(8 * q + 1));
    int k = (int)((s - 1.0f) * 0.5f);
    while ((k + 1) * (k + 2) / 2 <= q) k++;
    while (k * (k + 1) / 2 > q) k--;
    r = 22 - k;
    c = 23 - (q - k * (k + 1) / 2);
}

__global__ __launch_bounds__(TPB, 3) void afm_kernel(
    const void* __restrict__ xraw,
    const float* __restrict__ embed_table,
    const float* __restrict__ linear_table,
    const float* __restrict__ linear_bias,
    const float* __restrict__ attn_W,
    const float* __restrict__ attn_b,
    const float* __restrict__ proj_w,
    const float* __restrict__ proj_b,
    const float* __restrict__ fc_w,
    const float* __restrict__ fc_b,
    float* __restrict__ out)
{
    __shared__ float s_emb[ED * NF];        // [e][f]
    __shared__ float4 s_wdup2[AS * 8];      // [a][e2] = {w[2e2][a],w[2e2][a],w[2e2+1][a],w[2e2+1][a]}
    __shared__ u64  s_bdup[AS];             // attn_b duplicated
    __shared__ float s_proj[AS];
    __shared__ float s_fc[ED];
    __shared__ u64  s_inner2[ED * NPACK];   // [e][pack]; float view = [e][288]
    __shared__ float s_part[AG * NPP];      // partial scores per a-group
    __shared__ int   s_gidx[NF];
    __shared__ float s_lin[NF];
    __shared__ float s_rmax[6], s_rs[6], s_rt[6];

    const int b   = blockIdx.x;
    const int tid = threadIdx.x;
    const int wid = tid >> 5;
    const int lid = tid & 31;

    // ---------- phase 0: stage tables ----------
    if (tid < NF) {
        long long xv;
        if (g_x64_flag) xv = ((const long long*)xraw)[(long long)b * NF + tid];
        else            xv = (long long)((const int*)xraw)[b * NF + tid];
        int g = (int)xv + tid * 50000;
        s_gidx[tid] = g;
        s_lin[tid]  = linear_table[g];
    }
    // W duplicated, two e's per float4: 256 entries
    #pragma unroll
    for (int i = tid; i < AS * 8; i += TPB) {
        int a = i >> 3, e2 = i & 7;
        float w0 = attn_W[(2 * e2) * AS + a];
        float w1 = attn_W[(2 * e2 + 1) * AS + a];
        s_wdup2[i] = make_float4(w0, w0, w1, w1);
    }
    if (tid < AS) {
        float bb = attn_b[tid];
        s_bdup[tid] = pack2(bb, bb);
        s_proj[tid] = proj_w[tid];
    }
    if (tid < ED) s_fc[tid] = fc_w[tid];
    __syncthreads();

    // embedding gather: [e][f], consecutive threads read consecutive e (coalesced)
    #pragma unroll
    for (int i = tid; i < NF * ED; i += TPB) {
        int f = i >> 4, e = i & 15;
        s_emb[e * NF + f] = embed_table[(long long)s_gidx[f] * ED + e];
    }
    __syncthreads();

    // ---------- phase 1: inner products into smem (packed pairs) ----------
    // u64 entry uidx = e*144 + pack; pack holds pairs (2*pack, 2*pack+1)
    #pragma unroll
    for (int t = 0; t < (ED * NPACK) / TPB; t++) {
        int uidx = tid + t * TPB;
        int e = uidx / NPACK, pk = uidx - e * NPACK;
        int p0 = 2 * pk;
        float v0 = 0.f, v1 = 0.f;
        if (p0 < NPAIR) {
            int r, c; pair_rc(p0, r, c);
            v0 = s_emb[e * NF + r] * s_emb[e * NF + c];
        }
        if (p0 + 1 < NPAIR) {
            int r, c; pair_rc(p0 + 1, r, c);
            v1 = s_emb[e * NF + r] * s_emb[e * NF + c];
        }
        s_inner2[uidx] = pack2(v0, v1);
    }
    __syncthreads();

    // ---------- phase 2: z = inner @ W + b (pair-packed f32x2 GEMM) ----------
    const int ag = tid / PG;           // 0..3 (8 a-values each)
    const int pg = tid - ag * PG;      // 0..47 (3 packs each)

    u64 acc[AR][PK];
    #pragma unroll
    for (int ai = 0; ai < AR; ai++)
        #pragma unroll
        for (int k = 0; k < PK; k++)
            acc[ai][k] = s_bdup[ag * AR + ai];

    #pragma unroll
    for (int e2 = 0; e2 < 8; e2++) {
        u64 in0[PK], in1[PK];
        #pragma unroll
        for (int k = 0; k < PK; k++) {
            in0[k] = s_inner2[(2 * e2) * NPACK + k * PG + pg];
            in1[k] = s_inner2[(2 * e2 + 1) * NPACK + k * PG + pg];
        }
        #pragma unroll
        for (int ai = 0; ai < AR; ai++) {
            float4 wq = s_wdup2[(ag * AR + ai) * 8 + e2];
            u64 wlo = pack2(wq.x, wq.y);   // (w_e0, w_e0)
            u64 whi = pack2(wq.z, wq.w);   // (w_e1, w_e1)
            #pragma unroll
            for (int k = 0; k < PK; k++) {
                acc[ai][k] = fma2(in0[k], wlo, acc[ai][k]);
                acc[ai][k] = fma2(in1[k], whi, acc[ai][k]);
            }
        }
    }

    // ---------- partial scores: relu(z) . proj over this thread's 8 a's ----------
    {
        float sp0[PK], sp1[PK];
        #pragma unroll
        for (int k = 0; k < PK; k++) { sp0[k] = 0.f; sp1[k] = 0.f; }
        #pragma unroll
        for (int ai = 0; ai < AR; ai++) {
            float pw = s_proj[ag * AR + ai];
            #pragma unroll
            for (int k = 0; k < PK; k++) {
                float lo, hi; unpack2(acc[ai][k], lo, hi);
                sp0[k] = fmaf(fmaxf(lo, 0.f), pw, sp0[k]);
                sp1[k] = fmaf(fmaxf(hi, 0.f), pw, sp1[k]);
            }
        }
        #pragma unroll
        for (int k = 0; k < PK; k++) {
            int p0 = 2 * (k * PG + pg);
            s_part[ag * NPP + p0]     = sp0[k];
            s_part[ag * NPP + p0 + 1] = sp1[k];
        }
    }
    __syncthreads();

    // ---------- scores, softmax over pairs, cross term ----------
    const float* s_innerf = (const float*)s_inner2;   // [e][288]
    const float pb = proj_b[0];

    float sc0 = -1e30f, sc1 = -1e30f, y0 = 0.f, y1 = 0.f;
    {
        int p = tid;
        if (p < NPAIR) {
            sc0 = s_part[p] + s_part[NPP + p] + s_part[2 * NPP + p] + s_part[3 * NPP + p] + pb;
            float y = 0.f;
            #pragma unroll
            for (int e = 0; e < ED; e++) y = fmaf(s_innerf[e * NPP + p], s_fc[e], y);
            y0 = y;
        }
        p = tid + TPB;
        if (p < NPAIR) {
            sc1 = s_part[p] + s_part[NPP + p] + s_part[2 * NPP + p] + s_part[3 * NPP + p] + pb;
            float y = 0.f;
            #pragma unroll
            for (int e = 0; e < ED; e++) y = fmaf(s_innerf[e * NPP + p], s_fc[e], y);
            y1 = y;
        }
    }

    // max
    float m = fmaxf(sc0, sc1);
    #pragma unroll
    for (int o = 16; o > 0; o >>= 1)
        m = fmaxf(m, __shfl_xor_sync(0xffffffffu, m, o));
    if (lid == 0) s_rmax[wid] = m;
    __syncthreads();
    float M = s_rmax[0];
    #pragma unroll
    for (int w = 1; w < 6; w++) M = fmaxf(M, s_rmax[w]);

    // sum of exp, sum of exp*y
    float e0 = __expf(sc0 - M);
    float e1 = __expf(sc1 - M);
    float S = e0 + e1;
    float T = fmaf(e0, y0, e1 * y1);
    #pragma unroll
    for (int o = 16; o > 0; o >>= 1) {
        S += __shfl_xor_sync(0xffffffffu, S, o);
        T += __shfl_xor_sync(0xffffffffu, T, o);
    }
    if (lid == 0) { s_rs[wid] = S; s_rt[wid] = T; }
    __syncthreads();

    if (tid == 0) {
        float SS = 0.f, TT = 0.f;
        #pragma unroll
        for (int w = 0; w < 6; w++) { SS += s_rs[w]; TT += s_rt[w]; }
        float lin = 0.f;
        #pragma unroll
        for (int f = 0; f < NF; f++) lin += s_lin[f];
        out[b] = lin + linear_bias[0] + TT / SS + fc_b[0];
    }
}

extern "C" void kernel_launch(void* const* d_in, const int* in_sizes, int n_in,
                              void* d_out, int out_size) {
    const void*  x            = d_in[0];
    const float* embed_table  = (const float*)d_in[1];
    const float* linear_table = (const float*)d_in[2];
    const float* linear_bias  = (const float*)d_in[3];
    const float* attn_W       = (const float*)d_in[4];
    const float* attn_b       = (const float*)d_in[5];
    const float* proj_w       = (const float*)d_in[6];
    const float* proj_b       = (const float*)d_in[7];
    const float* fc_w         = (const float*)d_in[8];
    const float* fc_b         = (const float*)d_in[9];
    float* out = (float*)d_out;

    int B = in_sizes[0] / NF;

    detect_dtype_kernel<<<1, 32>>>((const unsigned int*)x);
    afm_kernel<<<B, TPB>>>(x, embed_table, linear_table, linear_bias,
                           attn_W, attn_b, proj_w, proj_b, fc_w, fc_b, out);
}